// round 5
// baseline (speedup 1.0000x reference)
#include <cuda_runtime.h>
#include <cstdint>

#define NB 64
#define NN 22
#define NF 64
#define NO 64
#define NT 512
#define TT 8              // t-tile width per CTA

typedef unsigned long long u64;

__device__ float d_S[2*NN*NN];   // Chebyshev supports S1, S2 (S0 = I implicit)

// ---------------------------------------------------------------------------
// packed f32x2 helpers (Blackwell)
// ---------------------------------------------------------------------------
__device__ __forceinline__ u64 pk2(float a, float b) {
    u64 r; asm("mov.b64 %0,{%1,%2};" : "=l"(r) : "f"(a), "f"(b)); return r;
}
__device__ __forceinline__ u64 ffma2(u64 a, u64 b, u64 c) {
    u64 d; asm("fma.rn.f32x2 %0,%1,%2,%3;" : "=l"(d) : "l"(a), "l"(b), "l"(c)); return d;
}
__device__ __forceinline__ u64 fmul2(u64 a, u64 b) {
    u64 d; asm("mul.rn.f32x2 %0,%1,%2;" : "=l"(d) : "l"(a), "l"(b)); return d;
}
__device__ __forceinline__ void unpk(u64 v, float& a, float& b) {
    asm("mov.b64 {%0,%1},%2;" : "=f"(a), "=f"(b) : "l"(v));
}

// ---------------------------------------------------------------------------
// K0: supports = softmax(relu(E E^T), axis=1); write S1=supports,
//     S2 = 2*S1@S1 - I.  One block, 512 threads.
// ---------------------------------------------------------------------------
__global__ void k_supports(const float* __restrict__ E) {
    __shared__ float Es[NN*NN];
    __shared__ float P[NN*NN];
    __shared__ float sup[NN*NN];
    int t = threadIdx.x;
    if (t < NN*NN) Es[t] = E[t];
    __syncthreads();
    if (t < NN*NN) {
        int i = t / NN, j = t % NN;
        float s = 0.f;
        #pragma unroll
        for (int l = 0; l < NN; l++) s += Es[i*NN + l] * Es[j*NN + l];
        P[t] = fmaxf(s, 0.f);
    }
    __syncthreads();
    if (t < NN) {
        float mx = -1e30f;
        #pragma unroll
        for (int j = 0; j < NN; j++) mx = fmaxf(mx, P[t*NN + j]);
        float den = 0.f;
        #pragma unroll
        for (int j = 0; j < NN; j++) { float e = expf(P[t*NN + j] - mx); sup[t*NN + j] = e; den += e; }
        float inv = 1.f / den;
        #pragma unroll
        for (int j = 0; j < NN; j++) sup[t*NN + j] *= inv;
    }
    __syncthreads();
    if (t < NN*NN) {
        int i = t / NN, j = t % NN;
        float eye = (i == j) ? 1.f : 0.f;
        d_S[t] = sup[t];                       // S1
        float s = 0.f;
        #pragma unroll
        for (int l = 0; l < NN; l++) s += sup[i*NN + l] * sup[l*NN + j];
        d_S[NN*NN + t] = 2.f * s - eye;        // S2
    }
}

// ---------------------------------------------------------------------------
// Main fused kernel: one CTA per (b, 8-wide t tile). 768 threads, occ 1.
// Stage:   a2d[kk][m][n] = dup(S[kk+1][n][m]*att[b][n][m]) (u64 pairs),
//          diag[m] = dup(att[b][m][m]), theta raw floats.
// Phase 1: rhs[k][m][f][t] = sum_n a2*x   (packed f32x2 over t, smem)
// Phase 2: out[b][m][o][t] = relu(sum_{k,f} theta[k][f][o]*rhs[k][m][f][t])
// ---------------------------------------------------------------------------
__global__ void __launch_bounds__(768, 1) k_main(
    const float* __restrict__ x,
    const float* __restrict__ att,
    const float* __restrict__ theta_g,
    float* __restrict__ out)
{
    extern __shared__ float sm[];
    float* rhs_s   = sm;                                   // [3][22][64][8] = 33792 f
    float* theta_s = sm + 3*NN*NF*TT;                      // [3][64][64]    = 12288 f
    u64*   a2d     = (u64*)(sm + 3*NN*NF*TT + 3*NF*NO);    // [2][22][22] u64 = 968
    u64*   diag    = a2d + 2*NN*NN;                        // [22] u64

    const int tid = threadIdx.x;
    const int b   = blockIdx.y;
    const int tt0 = blockIdx.x * TT;

    // ---- stage theta (raw floats) + A2 (duplicated u64 pairs) ----
    {
        const float4* tg = (const float4*)theta_g;
        float4* ts = (float4*)theta_s;
        #pragma unroll
        for (int j = 0; j < 4; j++) ts[tid + j*768] = tg[tid + j*768];
    }
    // FIX (R4 bug): 990 staging items > 768 threads -> grid-stride loop
    for (int idx = tid; idx < 2*NN*NN + NN; idx += 768) {
        if (idx < 2*NN*NN) {
            int kk = idx / (NN*NN);
            int r  = idx % (NN*NN);
            int m = r / NN, n = r % NN;
            float v = d_S[kk*NN*NN + n*NN + m] * att[(b*NN + n)*NN + m];
            a2d[idx] = pk2(v, v);
        } else {
            int m = idx - 2*NN*NN;
            float v = att[(b*NN + m)*NN + m];
            diag[m] = pk2(v, v);
        }
    }
    __syncthreads();

    // ---- phase 1: thread = (k, f, t-pair); 3*64*4 = 768 items ----
    const float* xb = x + (size_t)b*NN*NF*NT + tt0;
    {
        const int k  = tid >> 8;           // warp-uniform
        const int f  = (tid >> 2) & 63;
        const int tp = tid & 3;
        float* rw = rhs_s + (size_t)(k*NN)*(NF*TT) + f*TT + tp*2;
        if (k == 0) {
            // S0 = I -> rhs[0][m] = diag[m] * x[m]
            #pragma unroll
            for (int m = 0; m < NN; m++) {
                u64 xv = *(const u64*)(xb + (m*NF + f)*NT + tp*2);
                *(u64*)(rw + m*(NF*TT)) = fmul2(diag[m], xv);
            }
        } else {
            u64 acc[NN];
            #pragma unroll
            for (int m = 0; m < NN; m++) acc[m] = 0ULL;
            const u64* ap = a2d + (k-1)*NN*NN;
            #pragma unroll 1
            for (int c = 0; c < NN/2; c++) {
                u64 xv0 = *(const u64*)(xb + ((2*c+0)*NF + f)*NT + tp*2);
                u64 xv1 = *(const u64*)(xb + ((2*c+1)*NF + f)*NT + tp*2);
                #pragma unroll
                for (int m = 0; m < NN; m++) {
                    ulonglong2 aa = *(const ulonglong2*)(ap + m*NN + 2*c);
                    acc[m] = ffma2(aa.x, xv0, acc[m]);
                    acc[m] = ffma2(aa.y, xv1, acc[m]);
                }
            }
            #pragma unroll
            for (int m = 0; m < NN; m++)
                *(u64*)(rw + m*(NF*TT)) = acc[m];
        }
    }
    __syncthreads();

    // ---- phase 2: warp = (m-pair, o-half); lane = (o-pair, t-half) ----
    const int w = tid >> 5;
    if (w < NN) {
        const int mb   = w >> 1;            // 0..10
        const int ob   = w & 1;             // 0..1
        const int lane = tid & 31;
        const int og   = lane >> 1;         // 0..15
        const int tp2  = lane & 1;          // 0..1
        const int m0   = mb * 2;
        const int o0   = ob * 32 + og * 2;

        u64 acc[2][2][2];                   // [mm][oo][t-pair]
        #pragma unroll
        for (int i = 0; i < 2; i++)
            #pragma unroll
            for (int j = 0; j < 2; j++)
                #pragma unroll
                for (int p = 0; p < 2; p++) acc[i][j][p] = 0ULL;

        #pragma unroll
        for (int k = 0; k < 3; k++) {
            const float* th = theta_s + k*NF*NO + o0;
            const float* r0 = rhs_s + (size_t)(k*NN + m0)*(NF*TT) + tp2*4;
            const float* r1 = r0 + NF*TT;
            #pragma unroll 8
            for (int f = 0; f < NF; f++) {
                float2 tv = *(const float2*)(th + f*NO);
                u64 t0 = pk2(tv.x, tv.x);
                u64 t1 = pk2(tv.y, tv.y);
                ulonglong2 ra = *(const ulonglong2*)(r0 + f*TT);
                ulonglong2 rb = *(const ulonglong2*)(r1 + f*TT);
                acc[0][0][0] = ffma2(t0, ra.x, acc[0][0][0]);
                acc[0][0][1] = ffma2(t0, ra.y, acc[0][0][1]);
                acc[1][0][0] = ffma2(t0, rb.x, acc[1][0][0]);
                acc[1][0][1] = ffma2(t0, rb.y, acc[1][0][1]);
                acc[0][1][0] = ffma2(t1, ra.x, acc[0][1][0]);
                acc[0][1][1] = ffma2(t1, ra.y, acc[0][1][1]);
                acc[1][1][0] = ffma2(t1, rb.x, acc[1][1][0]);
                acc[1][1][1] = ffma2(t1, rb.y, acc[1][1][1]);
            }
        }

        // epilogue: unpack, relu, float4 stores (4 t contiguous per acc pair)
        #pragma unroll
        for (int mm = 0; mm < 2; mm++) {
            #pragma unroll
            for (int oo = 0; oo < 2; oo++) {
                float v0, v1, v2, v3;
                unpk(acc[mm][oo][0], v0, v1);
                unpk(acc[mm][oo][1], v2, v3);
                float* op = out + ((size_t)(b*NN + m0 + mm)*NO + o0 + oo)*NT
                                + tt0 + tp2*4;
                *(float4*)op = make_float4(fmaxf(v0, 0.f), fmaxf(v1, 0.f),
                                           fmaxf(v2, 0.f), fmaxf(v3, 0.f));
            }
        }
    }
}

// ---------------------------------------------------------------------------
extern "C" void kernel_launch(void* const* d_in, const int* in_sizes, int n_in,
                              void* d_out, int out_size)
{
    const float* x     = (const float*)d_in[0];   // [B,N,F_in,T]
    const float* att   = (const float*)d_in[1];   // [B,N,N]
    const float* theta = (const float*)d_in[2];   // [K,F_in,F_out]
    const float* emb   = (const float*)d_in[3];   // [N,N]
    float* out = (float*)d_out;                   // [B,N,F_out,T]

    k_supports<<<1, 512>>>(emb);

    size_t smem = (size_t)(3*NN*NF*TT + 3*NF*NO) * sizeof(float)
                + (size_t)(2*NN*NN + NN) * sizeof(u64);
    cudaFuncSetAttribute(k_main, cudaFuncAttributeMaxDynamicSharedMemorySize, (int)smem);
    dim3 grid(NT/TT, NB);
    k_main<<<grid, 768, smem>>>(x, att, theta, out);
}